// round 12
// baseline (speedup 1.0000x reference)
#include <cuda_runtime.h>
#include <math.h>
#include <stdint.h>

#define Bsz  4
#define Cdim 512
#define HCd  64
#define Npix 4096

// ---- scratch (static device allocations; no cudaMalloc allowed) ----
__device__ float g_scale[4];                 // 1/sigma for Wf, Wg, Wh, Wv
__device__ float g_f[Bsz * Npix * HCd];      // [B][N][HC]
__device__ float g_g[Bsz * Npix * HCd];
__device__ float g_h[Bsz * Npix * HCd];
__device__ float g_o[Bsz * Npix * HCd];

// ---- mma helper: tf32 m16n8k8 (raw fp32 bits in; HW truncates mantissa) ----
__device__ __forceinline__ void mma8(float* c, const uint32_t* a, const uint32_t* b) {
    asm volatile(
        "mma.sync.aligned.m16n8k8.row.col.f32.tf32.tf32.f32 "
        "{%0,%1,%2,%3}, {%4,%5,%6,%7}, {%8,%9}, {%0,%1,%2,%3};"
        : "+f"(c[0]), "+f"(c[1]), "+f"(c[2]), "+f"(c[3])
        : "r"(a[0]), "r"(a[1]), "r"(a[2]), "r"(a[3]), "r"(b[0]), "r"(b[1]));
}

__device__ __forceinline__ void cp16(void* sdst, const void* gsrc) {
    uint32_t s = (uint32_t)__cvta_generic_to_shared(sdst);
    asm volatile("cp.async.cg.shared.global [%0], [%1], 16;" :: "r"(s), "l"(gsrc));
}

// ============================================================================
// 1) sigma = ||W (W^T u)|| / ||W^T u||   ->  store 1/sigma
// ============================================================================
__global__ void sigma_kernel(const float* __restrict__ Wf, const float* __restrict__ uf,
                             const float* __restrict__ Wg, const float* __restrict__ ug,
                             const float* __restrict__ Wh, const float* __restrict__ uh,
                             const float* __restrict__ Wv, const float* __restrict__ uv) {
    __shared__ float su[512];
    __shared__ float sv[512];
    __shared__ float sred[512];
    __shared__ float s_nv2;

    int idx = blockIdx.x;
    const float* W; const float* u; int R, Cn;
    if (idx == 0)      { W = Wf; u = uf; R = 64;  Cn = 512; }
    else if (idx == 1) { W = Wg; u = ug; R = 64;  Cn = 512; }
    else if (idx == 2) { W = Wh; u = uh; R = 64;  Cn = 512; }
    else               { W = Wv; u = uv; R = 512; Cn = 64;  }

    int t = threadIdx.x;
    if (t < R) su[t] = u[t];
    __syncthreads();

    float nv2p = 0.f;
    for (int c = t; c < Cn; c += 512) {
        float acc = 0.f;
        for (int r = 0; r < R; r++) acc += W[r * Cn + c] * su[r];
        sv[c] = acc;
        nv2p += acc * acc;
    }
    sred[t] = nv2p;
    __syncthreads();
    for (int s = 256; s > 0; s >>= 1) { if (t < s) sred[t] += sred[t + s]; __syncthreads(); }
    if (t == 0) s_nv2 = sred[0];
    __syncthreads();

    float nw2p = 0.f;
    for (int r = t; r < R; r += 512) {
        float acc = 0.f;
        for (int c = 0; c < Cn; c++) acc += W[r * Cn + c] * sv[c];
        nw2p += acc * acc;
    }
    sred[t] = nw2p;
    __syncthreads();
    for (int s = 256; s > 0; s >>= 1) { if (t < s) sred[t] += sred[t + s]; __syncthreads(); }
    if (t == 0) g_scale[idx] = sqrtf(s_nv2 / sred[0]);   // 1/sigma
}

// ============================================================================
// 2) Projections via tf32 mma, ONE matrix per CTA (blockIdx.z = f/g/h).
// ============================================================================
__global__ void __launch_bounds__(256) fgh_mma_kernel(
    const float* __restrict__ x,
    const float* __restrict__ Wf, const float* __restrict__ bf,
    const float* __restrict__ Wg, const float* __restrict__ bg,
    const float* __restrict__ Wh, const float* __restrict__ bh) {
    __shared__ float xs[128 * 36];   // [pix][c]
    __shared__ float ws[64 * 36];    // [outRow][c], scale folded

    int b = blockIdx.y;
    int n0 = blockIdx.x * 128;
    int mat = blockIdx.z;
    int tid = threadIdx.x;
    int warp = tid >> 5, lane = tid & 31;
    int gr = lane >> 2, tg = lane & 3;
    int qr = warp * 16;

    const float* W; const float* bias; float* dst; float sc;
    if (mat == 0)      { W = Wf; bias = bf; dst = g_f; sc = g_scale[0]; }
    else if (mat == 1) { W = Wg; bias = bg; dst = g_g; sc = g_scale[1]; }
    else               { W = Wh; bias = bh; dst = g_h; sc = g_scale[2]; }

    float acc[8][4];
    #pragma unroll
    for (int nt = 0; nt < 8; nt++) acc[nt][0] = acc[nt][1] = acc[nt][2] = acc[nt][3] = 0.f;

    for (int c0 = 0; c0 < Cdim; c0 += 32) {
        __syncthreads();
        #pragma unroll
        for (int i = 0; i < 16; i++) {
            int id = tid + i * 256;
            int cc = id >> 7, nn = id & 127;
            xs[nn * 36 + cc] = x[((size_t)b * Cdim + c0 + cc) * Npix + n0 + nn];
        }
        #pragma unroll
        for (int i = 0; i < 8; i++) {
            int id = tid + i * 256;
            int row = id >> 5, cc = id & 31;
            ws[row * 36 + cc] = W[row * Cdim + c0 + cc] * sc;
        }
        __syncthreads();

        uint32_t a[4][4];
        #pragma unroll
        for (int kt = 0; kt < 4; kt++) {
            int c = kt * 8 + tg;
            a[kt][0] = __float_as_uint(xs[(qr + gr) * 36 + c]);
            a[kt][1] = __float_as_uint(xs[(qr + gr + 8) * 36 + c]);
            a[kt][2] = __float_as_uint(xs[(qr + gr) * 36 + c + 4]);
            a[kt][3] = __float_as_uint(xs[(qr + gr + 8) * 36 + c + 4]);
        }
        #pragma unroll
        for (int nt = 0; nt < 8; nt++) {
            #pragma unroll
            for (int kt = 0; kt < 4; kt++) {
                uint32_t bb[2];
                int rw = nt * 8 + gr, c = kt * 8 + tg;
                bb[0] = __float_as_uint(ws[rw * 36 + c]);
                bb[1] = __float_as_uint(ws[rw * 36 + c + 4]);
                mma8(acc[nt], a[kt], bb);
            }
        }
    }

    int row0 = n0 + qr + gr, row1 = row0 + 8;
    #pragma unroll
    for (int nt = 0; nt < 8; nt++) {
        int lcol = nt * 8 + 2 * tg;
        float b0 = bias[lcol], b1 = bias[lcol + 1];
        *(float2*)&dst[((size_t)b * Npix + row0) * HCd + lcol] =
            make_float2(acc[nt][0] + b0, acc[nt][1] + b1);
        *(float2*)&dst[((size_t)b * Npix + row1) * HCd + lcol] =
            make_float2(acc[nt][2] + b0, acc[nt][3] + b1);
    }
}

// ============================================================================
// 3) Flash attention, tf32 mma, software-pipelined S-GEMM:
//    iteration t issues S(t+1) HMMAs first, then softmax(t) runs while the
//    tensor pipe drains, then PV(t). cp.async 3-slot ring, 1 barrier/tile.
// ============================================================================
#define QT 128
#define KT 64
#define NTILES (Npix / KT)

__global__ void __launch_bounds__(256, 1) attn_mma_kernel() {
    extern __shared__ float smem[];
    float* qs = smem;                   // [128][68]
    float* ksb = qs + QT * 68;          // 3 x [64][68]
    float* vsb = ksb + 3 * KT * 68;     // 3 x [64][72]
    float* ps = vsb + 3 * KT * 72;      // [128][68]

    int b = blockIdx.y;
    int q0g = blockIdx.x * QT;
    int tid = threadIdx.x;
    int warp = tid >> 5, lane = tid & 31;
    int gr = lane >> 2, tg = lane & 3;
    int qr = warp * 16;

    int prow[4], pc4[4];
    #pragma unroll
    for (int i = 0; i < 4; i++) {
        int id = tid + i * 256;
        prow[i] = id >> 4; pc4[i] = (id & 15) * 4;
    }
    const float* gK = g_g + (size_t)b * Npix * HCd;
    const float* gV = g_h + (size_t)b * Npix * HCd;

    // prologue: prefetch tiles 0 and 1
    #pragma unroll
    for (int st = 0; st < 2; st++) {
        float* kd = ksb + st * KT * 68;
        float* vd = vsb + st * KT * 72;
        #pragma unroll
        for (int i = 0; i < 4; i++) {
            size_t gb = (size_t)(st * KT + prow[i]) * HCd + pc4[i];
            cp16(&kd[prow[i] * 68 + pc4[i]], gK + gb);
            cp16(&vd[prow[i] * 72 + pc4[i]], gV + gb);
        }
        asm volatile("cp.async.commit_group;");
    }

    // Q tile
    #pragma unroll
    for (int i = 0; i < 8; i++) {
        int id = tid + i * 256;
        int row = id >> 4, c4 = (id & 15) * 4;
        *(float4*)&qs[row * 68 + c4] =
            *(const float4*)&g_f[((size_t)b * Npix + q0g + row) * HCd + c4];
    }
    asm volatile("cp.async.wait_group 1;");   // tile 0 resident
    __syncthreads();

    // hoisted Q fragments
    uint32_t a[8][4];
    #pragma unroll
    for (int kt = 0; kt < 8; kt++) {
        int c = kt * 8 + tg;
        a[kt][0] = __float_as_uint(qs[(qr + gr) * 68 + c]);
        a[kt][1] = __float_as_uint(qs[(qr + gr + 8) * 68 + c]);
        a[kt][2] = __float_as_uint(qs[(qr + gr) * 68 + c + 4]);
        a[kt][3] = __float_as_uint(qs[(qr + gr + 8) * 68 + c + 4]);
    }

    // S(0)
    float scur[8][4];
    #pragma unroll
    for (int nt = 0; nt < 8; nt++) scur[nt][0] = scur[nt][1] = scur[nt][2] = scur[nt][3] = 0.f;
    #pragma unroll
    for (int kt = 0; kt < 8; kt++) {
        #pragma unroll
        for (int nt = 0; nt < 8; nt++) {
            uint32_t bb[2];
            int n = nt * 8 + gr, c = kt * 8 + tg;
            bb[0] = __float_as_uint(ksb[n * 68 + c]);
            bb[1] = __float_as_uint(ksb[n * 68 + c + 4]);
            mma8(scur[nt], a[kt], bb);
        }
    }

    float o[8][4];
    #pragma unroll
    for (int dt = 0; dt < 8; dt++) { o[dt][0] = o[dt][1] = o[dt][2] = o[dt][3] = 0.f; }
    float rmax0 = -1e30f, rmax1 = -1e30f, rsum0 = 0.f, rsum1 = 0.f;

    for (int t = 0; t < NTILES; t++) {
        // tile t+1 is the only possibly-pending cp.async group
        if (t + 1 < NTILES) asm volatile("cp.async.wait_group 0;");
        __syncthreads();   // all warps past iter t-1 smem reads; tile t+1 visible

        // prefetch tile t+2 into slot (t+2)%3  (== slot (t-1)%3, free)
        if (t + 2 < NTILES) {
            int st = (t + 2) % 3;
            float* kd = ksb + st * KT * 68;
            float* vd = vsb + st * KT * 72;
            int m0 = (t + 2) * KT;
            #pragma unroll
            for (int i = 0; i < 4; i++) {
                size_t gb = (size_t)(m0 + prow[i]) * HCd + pc4[i];
                cp16(&kd[prow[i] * 68 + pc4[i]], gK + gb);
                cp16(&vd[prow[i] * 72 + pc4[i]], gV + gb);
            }
            asm volatile("cp.async.commit_group;");
        }

        // ---- issue S(t+1) HMMAs first (drain under softmax below) ----
        float snext[8][4];
        if (t + 1 < NTILES) {
            const float* ksN = ksb + ((t + 1) % 3) * KT * 68;
            #pragma unroll
            for (int nt = 0; nt < 8; nt++)
                snext[nt][0] = snext[nt][1] = snext[nt][2] = snext[nt][3] = 0.f;
            #pragma unroll
            for (int kt = 0; kt < 8; kt++) {
                #pragma unroll
                for (int nt = 0; nt < 8; nt++) {
                    uint32_t bb[2];
                    int n = nt * 8 + gr, c = kt * 8 + tg;
                    bb[0] = __float_as_uint(ksN[n * 68 + c]);
                    bb[1] = __float_as_uint(ksN[n * 68 + c + 4]);
                    mma8(snext[nt], a[kt], bb);
                }
            }
        }

        // ---- softmax on scur (tile t), independent of snext mmas ----
        float tm0 = -1e30f, tm1 = -1e30f;
        #pragma unroll
        for (int nt = 0; nt < 8; nt++) {
            tm0 = fmaxf(tm0, fmaxf(scur[nt][0], scur[nt][1]));
            tm1 = fmaxf(tm1, fmaxf(scur[nt][2], scur[nt][3]));
        }
        tm0 = fmaxf(tm0, __shfl_xor_sync(0xffffffffu, tm0, 1));
        tm0 = fmaxf(tm0, __shfl_xor_sync(0xffffffffu, tm0, 2));
        tm1 = fmaxf(tm1, __shfl_xor_sync(0xffffffffu, tm1, 1));
        tm1 = fmaxf(tm1, __shfl_xor_sync(0xffffffffu, tm1, 2));
        float nm0 = fmaxf(rmax0, tm0), nm1 = fmaxf(rmax1, tm1);
        float corr0 = __expf(rmax0 - nm0), corr1 = __expf(rmax1 - nm1);
        float ts0 = 0.f, ts1 = 0.f;
        #pragma unroll
        for (int nt = 0; nt < 8; nt++) {
            scur[nt][0] = __expf(scur[nt][0] - nm0);
            scur[nt][1] = __expf(scur[nt][1] - nm0);
            scur[nt][2] = __expf(scur[nt][2] - nm1);
            scur[nt][3] = __expf(scur[nt][3] - nm1);
            ts0 += scur[nt][0] + scur[nt][1];
            ts1 += scur[nt][2] + scur[nt][3];
        }
        ts0 += __shfl_xor_sync(0xffffffffu, ts0, 1);
        ts0 += __shfl_xor_sync(0xffffffffu, ts0, 2);
        ts1 += __shfl_xor_sync(0xffffffffu, ts1, 1);
        ts1 += __shfl_xor_sync(0xffffffffu, ts1, 2);
        rsum0 = rsum0 * corr0 + ts0; rmax0 = nm0;
        rsum1 = rsum1 * corr1 + ts1; rmax1 = nm1;
        // deferred o-rescale: skip when running max unchanged (corr == 1.0 exactly)
        if (__any_sync(0xffffffffu, (corr0 != 1.f) | (corr1 != 1.f))) {
            #pragma unroll
            for (int dt = 0; dt < 8; dt++) {
                o[dt][0] *= corr0; o[dt][1] *= corr0;
                o[dt][2] *= corr1; o[dt][3] *= corr1;
            }
        }

        // ---- P -> smem (own warp rows), reload as A frags ----
        #pragma unroll
        for (int nt = 0; nt < 8; nt++) {
            *(float2*)&ps[(qr + gr) * 68 + nt * 8 + 2 * tg] =
                make_float2(scur[nt][0], scur[nt][1]);
            *(float2*)&ps[(qr + gr + 8) * 68 + nt * 8 + 2 * tg] =
                make_float2(scur[nt][2], scur[nt][3]);
        }
        __syncwarp();
        uint32_t pa[8][4];
        #pragma unroll
        for (int kt = 0; kt < 8; kt++) {
            int c = kt * 8 + tg;
            pa[kt][0] = __float_as_uint(ps[(qr + gr) * 68 + c]);
            pa[kt][1] = __float_as_uint(ps[(qr + gr + 8) * 68 + c]);
            pa[kt][2] = __float_as_uint(ps[(qr + gr) * 68 + c + 4]);
            pa[kt][3] = __float_as_uint(ps[(qr + gr + 8) * 68 + c + 4]);
        }

        // ---- O += P V  (tile t) ----
        const float* vs = vsb + (t % 3) * KT * 72;
        #pragma unroll
        for (int kt = 0; kt < 8; kt++) {
            #pragma unroll
            for (int dt = 0; dt < 8; dt++) {
                uint32_t bb[2];
                bb[0] = __float_as_uint(vs[(kt * 8 + tg) * 72 + dt * 8 + gr]);
                bb[1] = __float_as_uint(vs[(kt * 8 + tg + 4) * 72 + dt * 8 + gr]);
                mma8(o[dt], pa[kt], bb);
            }
        }

        // rotate score buffers
        if (t + 1 < NTILES) {
            #pragma unroll
            for (int nt = 0; nt < 8; nt++) {
                scur[nt][0] = snext[nt][0]; scur[nt][1] = snext[nt][1];
                scur[nt][2] = snext[nt][2]; scur[nt][3] = snext[nt][3];
            }
        }
    }

    float inv0 = 1.f / rsum0, inv1 = 1.f / rsum1;
    #pragma unroll
    for (int dt = 0; dt < 8; dt++) {
        size_t r0 = ((size_t)b * Npix + q0g + qr + gr) * HCd + dt * 8 + 2 * tg;
        *(float2*)&g_o[r0] = make_float2(o[dt][0] * inv0, o[dt][1] * inv0);
        size_t r1 = ((size_t)b * Npix + q0g + qr + gr + 8) * HCd + dt * 8 + 2 * tg;
        *(float2*)&g_o[r1] = make_float2(o[dt][2] * inv1, o[dt][3] * inv1);
    }
}

// ============================================================================
// 4) out = gamma * (Wv_sn @ o + bv) + x   (fp32, verified)
// ============================================================================
__global__ void __launch_bounds__(256) outproj_kernel(
    const float* __restrict__ x, const float* __restrict__ Wv,
    const float* __restrict__ bv, const float* __restrict__ gamma,
    float* __restrict__ out) {
    __shared__ float ot[64 * 68];
    __shared__ float wvs[64 * 68];

    int b = blockIdx.z;
    int c0 = blockIdx.y * 64;
    int n0 = blockIdx.x * 64;
    int t = threadIdx.x;
    int tx = t & 15, ty = t >> 4;
    float sv = g_scale[3];

    #pragma unroll
    for (int i = 0; i < 16; i++) {
        int id = t + i * 256;
        int r = id >> 6, qq = id & 63;
        ot[qq * 68 + r] = g_o[((size_t)b * Npix + n0 + r) * HCd + qq];
        wvs[r * 68 + qq] = Wv[(size_t)(c0 + r) * HCd + qq] * sv;
    }
    __syncthreads();

    float acc[4][4] = {{0}};
    #pragma unroll 8
    for (int k = 0; k < 64; k++) {
        float4 ov = *(const float4*)&ot[k * 68 + tx * 4];
        #pragma unroll
        for (int ci = 0; ci < 4; ci++) {
            float w = wvs[(ty * 4 + ci) * 68 + k];
            acc[ci][0] += w * ov.x; acc[ci][1] += w * ov.y;
            acc[ci][2] += w * ov.z; acc[ci][3] += w * ov.w;
        }
    }

    float gm = gamma[0];
    #pragma unroll
    for (int ci = 0; ci < 4; ci++) {
        int c = c0 + ty * 4 + ci;
        float bias = bv[c];
        size_t gi = ((size_t)b * Cdim + c) * Npix + n0 + tx * 4;
        float4 xin = *(const float4*)&x[gi];
        float4 r;
        r.x = gm * (acc[ci][0] + bias) + xin.x;
        r.y = gm * (acc[ci][1] + bias) + xin.y;
        r.z = gm * (acc[ci][2] + bias) + xin.z;
        r.w = gm * (acc[ci][3] + bias) + xin.w;
        *(float4*)&out[gi] = r;
    }
}

// ============================================================================
// launcher
// ============================================================================
extern "C" void kernel_launch(void* const* d_in, const int* in_sizes, int n_in,
                              void* d_out, int out_size) {
    (void)in_sizes; (void)n_in; (void)out_size;
    const float* x  = (const float*)d_in[0];
    const float* Wf = (const float*)d_in[1];
    const float* bf = (const float*)d_in[2];
    const float* Wg = (const float*)d_in[3];
    const float* bg = (const float*)d_in[4];
    const float* Wh = (const float*)d_in[5];
    const float* bh = (const float*)d_in[6];
    const float* Wv = (const float*)d_in[7];
    const float* bv = (const float*)d_in[8];
    const float* uf = (const float*)d_in[9];
    const float* ug = (const float*)d_in[10];
    const float* uh = (const float*)d_in[11];
    const float* uv = (const float*)d_in[12];
    const float* gamma = (const float*)d_in[13];
    float* out = (float*)d_out;

    static int attrs_set = 0;
    const int attn_smem =
        (QT * 68 + 3 * KT * 68 + 3 * KT * 72 + QT * 68) * (int)sizeof(float); // 177152
    if (!attrs_set) {
        cudaFuncSetAttribute(attn_mma_kernel, cudaFuncAttributeMaxDynamicSharedMemorySize,
                             attn_smem);
        attrs_set = 1;
    }

    sigma_kernel<<<4, 512>>>(Wf, uf, Wg, ug, Wh, uh, Wv, uv);
    fgh_mma_kernel<<<dim3(Npix / 128, Bsz, 3), 256>>>(x, Wf, bf, Wg, bg, Wh, bh);
    attn_mma_kernel<<<dim3(Npix / QT, Bsz), 256, attn_smem>>>();
    outproj_kernel<<<dim3(Npix / 64, Cdim / 64, Bsz), 256>>>(x, Wv, bv, gamma, out);
}

// round 13
// speedup vs baseline: 1.2686x; 1.2686x over previous
#include <cuda_runtime.h>
#include <cuda_fp16.h>
#include <math.h>
#include <stdint.h>

#define Bsz  4
#define Cdim 512
#define HCd  64
#define Npix 4096

// ---- scratch (static device allocations; no cudaMalloc allowed) ----
__device__ float  g_scale[4];                  // 1/sigma for Wf, Wg, Wh, Wv
__device__ __half g_fh[Bsz * Npix * HCd];      // Q  [B][N][HC] fp16
__device__ __half g_gh[Bsz * Npix * HCd];      // K  [B][N][HC] fp16
__device__ __half g_vhT[Bsz * HCd * Npix];     // V^T [B][HC][N] fp16
__device__ float  g_o[Bsz * Npix * HCd];       // attention out [B][N][HC]

// ---- fp16 mma m16n8k16, fp32 accum ----
__device__ __forceinline__ void mma16(float* c, const uint32_t* a,
                                      uint32_t b0, uint32_t b1) {
    asm volatile(
        "mma.sync.aligned.m16n8k16.row.col.f32.f16.f16.f32 "
        "{%0,%1,%2,%3}, {%4,%5,%6,%7}, {%8,%9}, {%0,%1,%2,%3};"
        : "+f"(c[0]), "+f"(c[1]), "+f"(c[2]), "+f"(c[3])
        : "r"(a[0]), "r"(a[1]), "r"(a[2]), "r"(a[3]), "r"(b0), "r"(b1));
}

// ---- tf32 mma m16n8k8 (kept for fgh) ----
__device__ __forceinline__ void mma8(float* c, const uint32_t* a, const uint32_t* b) {
    asm volatile(
        "mma.sync.aligned.m16n8k8.row.col.f32.tf32.tf32.f32 "
        "{%0,%1,%2,%3}, {%4,%5,%6,%7}, {%8,%9}, {%0,%1,%2,%3};"
        : "+f"(c[0]), "+f"(c[1]), "+f"(c[2]), "+f"(c[3])
        : "r"(a[0]), "r"(a[1]), "r"(a[2]), "r"(a[3]), "r"(b[0]), "r"(b[1]));
}

__device__ __forceinline__ void cp16(void* sdst, const void* gsrc) {
    uint32_t s = (uint32_t)__cvta_generic_to_shared(sdst);
    asm volatile("cp.async.cg.shared.global [%0], [%1], 16;" :: "r"(s), "l"(gsrc));
}

__device__ __forceinline__ uint32_t packh2(float lo, float hi) {
    __half2 h = __floats2half2_rn(lo, hi);
    return *(uint32_t*)&h;
}

// ============================================================================
// 1) sigma = ||W (W^T u)|| / ||W^T u||   ->  store 1/sigma
// ============================================================================
__global__ void sigma_kernel(const float* __restrict__ Wf, const float* __restrict__ uf,
                             const float* __restrict__ Wg, const float* __restrict__ ug,
                             const float* __restrict__ Wh, const float* __restrict__ uh,
                             const float* __restrict__ Wv, const float* __restrict__ uv) {
    __shared__ float su[512];
    __shared__ float sv[512];
    __shared__ float sred[512];
    __shared__ float s_nv2;

    int idx = blockIdx.x;
    const float* W; const float* u; int R, Cn;
    if (idx == 0)      { W = Wf; u = uf; R = 64;  Cn = 512; }
    else if (idx == 1) { W = Wg; u = ug; R = 64;  Cn = 512; }
    else if (idx == 2) { W = Wh; u = uh; R = 64;  Cn = 512; }
    else               { W = Wv; u = uv; R = 512; Cn = 64;  }

    int t = threadIdx.x;
    if (t < R) su[t] = u[t];
    __syncthreads();

    float nv2p = 0.f;
    for (int c = t; c < Cn; c += 512) {
        float acc = 0.f;
        for (int r = 0; r < R; r++) acc += W[r * Cn + c] * su[r];
        sv[c] = acc;
        nv2p += acc * acc;
    }
    sred[t] = nv2p;
    __syncthreads();
    for (int s = 256; s > 0; s >>= 1) { if (t < s) sred[t] += sred[t + s]; __syncthreads(); }
    if (t == 0) s_nv2 = sred[0];
    __syncthreads();

    float nw2p = 0.f;
    for (int r = t; r < R; r += 512) {
        float acc = 0.f;
        for (int c = 0; c < Cn; c++) acc += W[r * Cn + c] * sv[c];
        nw2p += acc * acc;
    }
    sred[t] = nw2p;
    __syncthreads();
    for (int s = 256; s > 0; s >>= 1) { if (t < s) sred[t] += sred[t + s]; __syncthreads(); }
    if (t == 0) g_scale[idx] = sqrtf(s_nv2 / sred[0]);   // 1/sigma
}

// ============================================================================
// 2) Projections via tf32 mma, ONE matrix per CTA (blockIdx.z = f/g/h).
//    Epilogue emits fp16: f,g as [n][d]; h TRANSPOSED as [d][n].
// ============================================================================
__global__ void __launch_bounds__(256) fgh_mma_kernel(
    const float* __restrict__ x,
    const float* __restrict__ Wf, const float* __restrict__ bf,
    const float* __restrict__ Wg, const float* __restrict__ bg,
    const float* __restrict__ Wh, const float* __restrict__ bh) {
    __shared__ float xs[128 * 36];   // [pix][c]
    __shared__ float ws[64 * 36];    // [outRow][c], scale folded

    int b = blockIdx.y;
    int n0 = blockIdx.x * 128;
    int mat = blockIdx.z;
    int tid = threadIdx.x;
    int warp = tid >> 5, lane = tid & 31;
    int gr = lane >> 2, tg = lane & 3;
    int qr = warp * 16;

    const float* W; const float* bias; float sc;
    if (mat == 0)      { W = Wf; bias = bf; sc = g_scale[0]; }
    else if (mat == 1) { W = Wg; bias = bg; sc = g_scale[1]; }
    else               { W = Wh; bias = bh; sc = g_scale[2]; }

    float acc[8][4];
    #pragma unroll
    for (int nt = 0; nt < 8; nt++) acc[nt][0] = acc[nt][1] = acc[nt][2] = acc[nt][3] = 0.f;

    for (int c0 = 0; c0 < Cdim; c0 += 32) {
        __syncthreads();
        #pragma unroll
        for (int i = 0; i < 16; i++) {
            int id = tid + i * 256;
            int cc = id >> 7, nn = id & 127;
            xs[nn * 36 + cc] = x[((size_t)b * Cdim + c0 + cc) * Npix + n0 + nn];
        }
        #pragma unroll
        for (int i = 0; i < 8; i++) {
            int id = tid + i * 256;
            int row = id >> 5, cc = id & 31;
            ws[row * 36 + cc] = W[row * Cdim + c0 + cc] * sc;
        }
        __syncthreads();

        uint32_t a[4][4];
        #pragma unroll
        for (int kt = 0; kt < 4; kt++) {
            int c = kt * 8 + tg;
            a[kt][0] = __float_as_uint(xs[(qr + gr) * 36 + c]);
            a[kt][1] = __float_as_uint(xs[(qr + gr + 8) * 36 + c]);
            a[kt][2] = __float_as_uint(xs[(qr + gr) * 36 + c + 4]);
            a[kt][3] = __float_as_uint(xs[(qr + gr + 8) * 36 + c + 4]);
        }
        #pragma unroll
        for (int nt = 0; nt < 8; nt++) {
            #pragma unroll
            for (int kt = 0; kt < 4; kt++) {
                uint32_t bb[2];
                int rw = nt * 8 + gr, c = kt * 8 + tg;
                bb[0] = __float_as_uint(ws[rw * 36 + c]);
                bb[1] = __float_as_uint(ws[rw * 36 + c + 4]);
                mma8(acc[nt], a[kt], bb);
            }
        }
    }

    int row0 = n0 + qr + gr, row1 = row0 + 8;
    if (mat < 2) {
        __half* dst = (mat == 0) ? g_fh : g_gh;
        #pragma unroll
        for (int nt = 0; nt < 8; nt++) {
            int lcol = nt * 8 + 2 * tg;
            float b0 = bias[lcol], b1 = bias[lcol + 1];
            __half2 v0 = __floats2half2_rn(acc[nt][0] + b0, acc[nt][1] + b1);
            __half2 v1 = __floats2half2_rn(acc[nt][2] + b0, acc[nt][3] + b1);
            *(__half2*)&dst[((size_t)b * Npix + row0) * HCd + lcol] = v0;
            *(__half2*)&dst[((size_t)b * Npix + row1) * HCd + lcol] = v1;
        }
    } else {
        // V transposed: g_vhT[b][d][n]
        #pragma unroll
        for (int nt = 0; nt < 8; nt++) {
            int d0 = nt * 8 + 2 * tg;
            float b0 = bias[d0], b1 = bias[d0 + 1];
            size_t r0 = ((size_t)b * HCd + d0) * Npix;
            size_t r1 = ((size_t)b * HCd + d0 + 1) * Npix;
            g_vhT[r0 + row0] = __float2half_rn(acc[nt][0] + b0);
            g_vhT[r1 + row0] = __float2half_rn(acc[nt][1] + b1);
            g_vhT[r0 + row1] = __float2half_rn(acc[nt][2] + b0);
            g_vhT[r1 + row1] = __float2half_rn(acc[nt][3] + b1);
        }
    }
}

// ============================================================================
// 3) Flash attention, fp16 m16n8k16 mma (half the HMMA count of tf32).
//    P stays in registers (S C-frags repack directly into PV A-frags).
//    cp.async 3-slot ring of 8KB half tiles; stride 72 halves (conflict-free).
// ============================================================================
#define QT 128
#define KT 64
#define NTILES (Npix / KT)
#define HSTR 72   // half-element stride per row

__global__ void __launch_bounds__(256, 1) attn_mma_kernel() {
    extern __shared__ __half hsm[];
    __half* ksb = hsm;                    // 3 x [64 keys][HSTR]
    __half* vsb = hsm + 3 * KT * HSTR;    // 3 x [64 d][HSTR keys]

    int b = blockIdx.y;
    int q0g = blockIdx.x * QT;
    int tid = threadIdx.x;
    int warp = tid >> 5, lane = tid & 31;
    int gr = lane >> 2, tg = lane & 3;
    int qr = warp * 16;

    // prefetch coords: 2 x (K row chunk + V row chunk) per thread
    int prow[2], pc8[2];
    #pragma unroll
    for (int i = 0; i < 2; i++) {
        int id = tid + i * 256;
        prow[i] = id >> 3; pc8[i] = (id & 7) * 8;
    }
    const __half* gK  = g_gh  + (size_t)b * Npix * HCd;
    const __half* gVt = g_vhT + (size_t)b * HCd * Npix;

    // prologue: prefetch tiles 0 and 1
    #pragma unroll
    for (int st = 0; st < 2; st++) {
        __half* kd = ksb + st * KT * HSTR;
        __half* vd = vsb + st * KT * HSTR;
        #pragma unroll
        for (int i = 0; i < 2; i++) {
            cp16(&kd[prow[i] * HSTR + pc8[i]],
                 gK + (size_t)(st * KT + prow[i]) * HCd + pc8[i]);
            cp16(&vd[prow[i] * HSTR + pc8[i]],
                 gVt + (size_t)prow[i] * Npix + st * KT + pc8[i]);
        }
        asm volatile("cp.async.commit_group;");
    }

    // Q fragments straight from global (held resident)
    uint32_t a[4][4];
    {
        const __half* q0 = g_fh + ((size_t)b * Npix + q0g + qr + gr) * HCd;
        const __half* q1 = q0 + 8 * HCd;
        #pragma unroll
        for (int kc = 0; kc < 4; kc++) {
            int d = kc * 16 + 2 * tg;
            a[kc][0] = *(const uint32_t*)&q0[d];
            a[kc][1] = *(const uint32_t*)&q1[d];
            a[kc][2] = *(const uint32_t*)&q0[d + 8];
            a[kc][3] = *(const uint32_t*)&q1[d + 8];
        }
    }

    float o[8][4];
    #pragma unroll
    for (int dt = 0; dt < 8; dt++) { o[dt][0] = o[dt][1] = o[dt][2] = o[dt][3] = 0.f; }
    float rmax0 = -1e30f, rmax1 = -1e30f, rsum0 = 0.f, rsum1 = 0.f;

    for (int t = 0; t < NTILES; t++) {
        if (t == NTILES - 1) asm volatile("cp.async.wait_group 0;");
        else                 asm volatile("cp.async.wait_group 1;");
        __syncthreads();   // tile t visible; slot (t+2)%3 free for reuse

        if (t + 2 < NTILES) {
            int st = (t + 2) % 3;
            __half* kd = ksb + st * KT * HSTR;
            __half* vd = vsb + st * KT * HSTR;
            int m0 = (t + 2) * KT;
            #pragma unroll
            for (int i = 0; i < 2; i++) {
                cp16(&kd[prow[i] * HSTR + pc8[i]],
                     gK + (size_t)(m0 + prow[i]) * HCd + pc8[i]);
                cp16(&vd[prow[i] * HSTR + pc8[i]],
                     gVt + (size_t)prow[i] * Npix + m0 + pc8[i]);
            }
            asm volatile("cp.async.commit_group;");
        }

        const __half* ks = ksb + (t % 3) * KT * HSTR;
        const __half* vs = vsb + (t % 3) * KT * HSTR;

        // ---- S = Q K^T  (4 k-chunks of 16 x 8 n-tiles) ----
        float s[8][4];
        #pragma unroll
        for (int nt = 0; nt < 8; nt++) { s[nt][0] = s[nt][1] = s[nt][2] = s[nt][3] = 0.f; }
        #pragma unroll
        for (int kc = 0; kc < 4; kc++) {
            #pragma unroll
            for (int nt = 0; nt < 8; nt++) {
                const __half* kr = &ks[(nt * 8 + gr) * HSTR + kc * 16 + 2 * tg];
                uint32_t b0 = *(const uint32_t*)kr;
                uint32_t b1 = *(const uint32_t*)(kr + 8);
                mma16(s[nt], a[kc], b0, b1);
            }
        }

        // ---- online softmax (rows gr, gr+8) ----
        float tm0 = -1e30f, tm1 = -1e30f;
        #pragma unroll
        for (int nt = 0; nt < 8; nt++) {
            tm0 = fmaxf(tm0, fmaxf(s[nt][0], s[nt][1]));
            tm1 = fmaxf(tm1, fmaxf(s[nt][2], s[nt][3]));
        }
        tm0 = fmaxf(tm0, __shfl_xor_sync(0xffffffffu, tm0, 1));
        tm0 = fmaxf(tm0, __shfl_xor_sync(0xffffffffu, tm0, 2));
        tm1 = fmaxf(tm1, __shfl_xor_sync(0xffffffffu, tm1, 1));
        tm1 = fmaxf(tm1, __shfl_xor_sync(0xffffffffu, tm1, 2));
        float nm0 = fmaxf(rmax0, tm0), nm1 = fmaxf(rmax1, tm1);
        float corr0 = __expf(rmax0 - nm0), corr1 = __expf(rmax1 - nm1);
        float ts0 = 0.f, ts1 = 0.f;
        #pragma unroll
        for (int nt = 0; nt < 8; nt++) {
            s[nt][0] = __expf(s[nt][0] - nm0);
            s[nt][1] = __expf(s[nt][1] - nm0);
            s[nt][2] = __expf(s[nt][2] - nm1);
            s[nt][3] = __expf(s[nt][3] - nm1);
            ts0 += s[nt][0] + s[nt][1];
            ts1 += s[nt][2] + s[nt][3];
        }
        ts0 += __shfl_xor_sync(0xffffffffu, ts0, 1);
        ts0 += __shfl_xor_sync(0xffffffffu, ts0, 2);
        ts1 += __shfl_xor_sync(0xffffffffu, ts1, 1);
        ts1 += __shfl_xor_sync(0xffffffffu, ts1, 2);
        rsum0 = rsum0 * corr0 + ts0; rmax0 = nm0;
        rsum1 = rsum1 * corr1 + ts1; rmax1 = nm1;
        if (__any_sync(0xffffffffu, (corr0 != 1.f) | (corr1 != 1.f))) {
            #pragma unroll
            for (int dt = 0; dt < 8; dt++) {
                o[dt][0] *= corr0; o[dt][1] *= corr0;
                o[dt][2] *= corr1; o[dt][3] *= corr1;
            }
        }

        // ---- O += P V : A-frags packed directly from S C-frags ----
        #pragma unroll
        for (int kc = 0; kc < 4; kc++) {
            uint32_t pa[4];
            pa[0] = packh2(s[2 * kc][0],     s[2 * kc][1]);
            pa[1] = packh2(s[2 * kc][2],     s[2 * kc][3]);
            pa[2] = packh2(s[2 * kc + 1][0], s[2 * kc + 1][1]);
            pa[3] = packh2(s[2 * kc + 1][2], s[2 * kc + 1][3]);
            #pragma unroll
            for (int dt = 0; dt < 8; dt++) {
                const __half* vr = &vs[(dt * 8 + gr) * HSTR + kc * 16 + 2 * tg];
                uint32_t b0 = *(const uint32_t*)vr;
                uint32_t b1 = *(const uint32_t*)(vr + 8);
                mma16(o[dt], pa, b0, b1);
            }
        }
    }

    float inv0 = 1.f / rsum0, inv1 = 1.f / rsum1;
    #pragma unroll
    for (int dt = 0; dt < 8; dt++) {
        size_t r0 = ((size_t)b * Npix + q0g + qr + gr) * HCd + dt * 8 + 2 * tg;
        *(float2*)&g_o[r0] = make_float2(o[dt][0] * inv0, o[dt][1] * inv0);
        size_t r1 = ((size_t)b * Npix + q0g + qr + gr + 8) * HCd + dt * 8 + 2 * tg;
        *(float2*)&g_o[r1] = make_float2(o[dt][2] * inv1, o[dt][3] * inv1);
    }
}

// ============================================================================
// 4) out = gamma * (Wv_sn @ o + bv) + x   (fp32, verified)
// ============================================================================
__global__ void __launch_bounds__(256) outproj_kernel(
    const float* __restrict__ x, const float* __restrict__ Wv,
    const float* __restrict__ bv, const float* __restrict__ gamma,
    float* __restrict__ out) {
    __shared__ float ot[64 * 68];
    __shared__ float wvs[64 * 68];

    int b = blockIdx.z;
    int c0 = blockIdx.y * 64;
    int n0 = blockIdx.x * 64;
    int t = threadIdx.x;
    int tx = t & 15, ty = t >> 4;
    float sv = g_scale[3];

    #pragma unroll
    for (int i = 0; i < 16; i++) {
        int id = t + i * 256;
        int r = id >> 6, qq = id & 63;
        ot[qq * 68 + r] = g_o[((size_t)b * Npix + n0 + r) * HCd + qq];
        wvs[r * 68 + qq] = Wv[(size_t)(c0 + r) * HCd + qq] * sv;
    }
    __syncthreads();

    float acc[4][4] = {{0}};
    #pragma unroll 8
    for (int k = 0; k < 64; k++) {
        float4 ov = *(const float4*)&ot[k * 68 + tx * 4];
        #pragma unroll
        for (int ci = 0; ci < 4; ci++) {
            float w = wvs[(ty * 4 + ci) * 68 + k];
            acc[ci][0] += w * ov.x; acc[ci][1] += w * ov.y;
            acc[ci][2] += w * ov.z; acc[ci][3] += w * ov.w;
        }
    }

    float gm = gamma[0];
    #pragma unroll
    for (int ci = 0; ci < 4; ci++) {
        int c = c0 + ty * 4 + ci;
        float bias = bv[c];
        size_t gi = ((size_t)b * Cdim + c) * Npix + n0 + tx * 4;
        float4 xin = *(const float4*)&x[gi];
        float4 r;
        r.x = gm * (acc[ci][0] + bias) + xin.x;
        r.y = gm * (acc[ci][1] + bias) + xin.y;
        r.z = gm * (acc[ci][2] + bias) + xin.z;
        r.w = gm * (acc[ci][3] + bias) + xin.w;
        *(float4*)&out[gi] = r;
    }
}

// ============================================================================
// launcher
// ============================================================================
extern "C" void kernel_launch(void* const* d_in, const int* in_sizes, int n_in,
                              void* d_out, int out_size) {
    (void)in_sizes; (void)n_in; (void)out_size;
    const float* x  = (const float*)d_in[0];
    const float* Wf = (const float*)d_in[1];
    const float* bf = (const float*)d_in[2];
    const float* Wg = (const float*)d_in[3];
    const float* bg = (const float*)d_in[4];
    const float* Wh = (const float*)d_in[5];
    const float* bh = (const float*)d_in[6];
    const float* Wv = (const float*)d_in[7];
    const float* bv = (const float*)d_in[8];
    const float* uf = (const float*)d_in[9];
    const float* ug = (const float*)d_in[10];
    const float* uh = (const float*)d_in[11];
    const float* uv = (const float*)d_in[12];
    const float* gamma = (const float*)d_in[13];
    float* out = (float*)d_out;

    static int attrs_set = 0;
    const int attn_smem = 6 * KT * HSTR * (int)sizeof(__half);  // 55296
    if (!attrs_set) {
        cudaFuncSetAttribute(attn_mma_kernel, cudaFuncAttributeMaxDynamicSharedMemorySize,
                             attn_smem);
        attrs_set = 1;
    }

    sigma_kernel<<<4, 512>>>(Wf, uf, Wg, ug, Wh, uh, Wv, uv);
    fgh_mma_kernel<<<dim3(Npix / 128, Bsz, 3), 256>>>(x, Wf, bf, Wg, bg, Wh, bh);
    attn_mma_kernel<<<dim3(Npix / QT, Bsz), 256, attn_smem>>>();
    outproj_kernel<<<dim3(Npix / 64, Cdim / 64, Bsz), 256>>>(x, Wv, bv, gamma, out);
}